// round 14
// baseline (speedup 1.0000x reference)
#include <cuda_runtime.h>
#include <stdint.h>

// Fp8Unpadding: gather un-padded rows out of a 256-row-padded concatenation.
// M_SPLITS = {1000,2300,512,3777,129,2048,900,1500}, HIDDEN=4096 (f32).
// dst row r maps to src row r + DELTA[group(r)]; DELTA constant per group.
//
// Row boundaries (cumulative m):  1000, 3300, 3812, 7589, 7718, 9766, 10666, 12166
// Row deltas:                        0,   24,   28,   28,   91,  218,   218,   342
//
// R14 probe: write-through stores (st.global.wt) on the final geometry
// (one 16KB row per CTA, TPB=128, 8x float4/thread front-batched, .cs loads).
// Output is never re-read; .wt avoids holding dirty lines in L2 — the LTS
// fabric is the measured binding limit (~6300 B/cyc), so any policy that
// lowers LTS residency-per-written-byte is the last candidate lever.

static constexpr int HIDDEN_V4  = 4096 / 4;   // 1024 float4 per row
static constexpr int TOTAL_ROWS = 12166;
static constexpr int UNROLL     = 8;
static constexpr int TPB        = 128;        // TPB * UNROLL = 1024 = 1 row

__device__ __forceinline__ int row_delta(int row)
{
    return (row < 1000)  ? 0
         : (row < 3300)  ? 24
         : (row < 7589)  ? 28
         : (row < 7718)  ? 91
         : (row < 10666) ? 218
         :                 342;
}

__device__ __forceinline__ void st128_wt(float4* p, const float4& r)
{
    asm volatile("st.global.wt.v4.f32 [%0], {%1,%2,%3,%4};"
                 :: "l"(p), "f"(r.x), "f"(r.y), "f"(r.z), "f"(r.w)
                 : "memory");
}

__global__ void __launch_bounds__(TPB)
unpad_gather_kernel(const float4* __restrict__ in, float4* __restrict__ out)
{
    int row = blockIdx.x;                        // one row per block
    const float4* __restrict__ src = in  + (row + row_delta(row)) * HIDDEN_V4;
    float4*       __restrict__ dst = out + row * HIDDEN_V4;

    float4 v[UNROLL];

    // front-batched independent loads (deep MLP), streaming policy
    #pragma unroll
    for (int j = 0; j < UNROLL; j++)
        v[j] = __ldcs(src + j * TPB + threadIdx.x);

    // write-through stores
    #pragma unroll
    for (int j = 0; j < UNROLL; j++)
        st128_wt(dst + j * TPB + threadIdx.x, v[j]);
}

extern "C" void kernel_launch(void* const* d_in, const int* in_sizes, int n_in,
                              void* d_out, int out_size)
{
    const float4* in  = (const float4*)d_in[0];   // f32 [12544, 4096]
    float4*       out = (float4*)d_out;           // f32 [12166, 4096]

    unpad_gather_kernel<<<TOTAL_ROWS, TPB>>>(in, out);
}

// round 15
// speedup vs baseline: 1.0264x; 1.0264x over previous
#include <cuda_runtime.h>
#include <stdint.h>

// Fp8Unpadding: gather un-padded rows out of a 256-row-padded concatenation.
// M_SPLITS = {1000,2300,512,3777,129,2048,900,1500}, HIDDEN=4096 (f32).
// dst row r maps to src row r + DELTA[group(r)]; DELTA constant per group.
//
// Row boundaries (cumulative m):  1000, 3300, 3812, 7589, 7718, 9766, 10666, 12166
// Row deltas:                        0,   24,   28,   28,   91,  218,   218,   342
//
// FINAL: one 16KB row per block. TPB=128, 8x float4 per thread = 1024 v4 =
// exactly 1 row. Block-uniform source delta, front-batched loads (MLP=8),
// streaming (.cs) policy both directions, zero tail, no bounds checks.
//
// Roofline status: pinned at the measured B300 LTS chip cap (~6300 B/cyc;
// peak observed 6304 GB/s = cap). Exhaustively verified saturated:
//   - MLP depth (1/8/16), issue order (batched/pipelined)
//   - access width (128/256-bit)
//   - cache policy (ld: default/.cs/.lu; st: default/.cs/.wt)
//   - grid shape (one-shot/persistent; 1-row/2-row CTAs)
//   - hardware path (SM vs copy engines)
// All converge at 54.5-56.2us kernel / 6.1-6.3 TB/s. Limit is the LTS fabric.

static constexpr int HIDDEN_V4  = 4096 / 4;   // 1024 float4 per row
static constexpr int TOTAL_ROWS = 12166;
static constexpr int UNROLL     = 8;
static constexpr int TPB        = 128;        // TPB * UNROLL = 1024 = 1 row

__device__ __forceinline__ int row_delta(int row)
{
    return (row < 1000)  ? 0
         : (row < 3300)  ? 24
         : (row < 7589)  ? 28
         : (row < 7718)  ? 91
         : (row < 10666) ? 218
         :                 342;
}

__global__ void __launch_bounds__(TPB)
unpad_gather_kernel(const float4* __restrict__ in, float4* __restrict__ out)
{
    int row = blockIdx.x;                        // one row per block
    const float4* __restrict__ src = in  + (row + row_delta(row)) * HIDDEN_V4;
    float4*       __restrict__ dst = out + row * HIDDEN_V4;

    float4 v[UNROLL];

    // front-batched independent loads (deep MLP)
    #pragma unroll
    for (int j = 0; j < UNROLL; j++)
        v[j] = __ldcs(src + j * TPB + threadIdx.x);

    #pragma unroll
    for (int j = 0; j < UNROLL; j++)
        __stcs(dst + j * TPB + threadIdx.x, v[j]);
}

extern "C" void kernel_launch(void* const* d_in, const int* in_sizes, int n_in,
                              void* d_out, int out_size)
{
    const float4* in  = (const float4*)d_in[0];   // f32 [12544, 4096]
    float4*       out = (float4*)d_out;           // f32 [12166, 4096]

    unpad_gather_kernel<<<TOTAL_ROWS, TPB>>>(in, out);
}